// round 11
// baseline (speedup 1.0000x reference)
#include <cuda_runtime.h>
#include <math_constants.h>

// ---------------------------------------------------------------------------
// MultiHeadSelfAttention: B=4, C=2048, E=1024, H=16, D=64  (all fp32)
//   qkv  = x @ w_qkv^T            (8192 x 3072)
//   attn = causal softmax(q k^T / sqrt(D)) v   per (b,h)
//   out  = flat @ w_out^T         (8192 x 1024)
// ---------------------------------------------------------------------------

#define BDIM    4
#define CDIM    2048
#define EDIM    1024
#define HDIM    16
#define DDIM    64
#define MROWS   (BDIM*CDIM)      // 8192
#define BH      (BDIM*HDIM)      // 64

// Scratch (device globals: allocation-free, graph-capturable)
__device__ float g_q[(size_t)BH*CDIM*DDIM];      // (B*H, C, D)
__device__ float g_k[(size_t)BH*CDIM*DDIM];
__device__ float g_v[(size_t)BH*CDIM*DDIM];
__device__ float g_attn[(size_t)MROWS*EDIM];     // (B*C, H*D)

// ---- Packed f32x2 helpers (Blackwell sm_103a; exact fp32 semantics) -------
__device__ __forceinline__ unsigned long long ffma2(unsigned long long a,
                                                    unsigned long long b,
                                                    unsigned long long c) {
    unsigned long long d;
    asm("fma.rn.f32x2 %0, %1, %2, %3;" : "=l"(d) : "l"(a), "l"(b), "l"(c));
    return d;
}
__device__ __forceinline__ unsigned long long fmul2(unsigned long long a,
                                                    unsigned long long b) {
    unsigned long long d;
    asm("mul.rn.f32x2 %0, %1, %2;" : "=l"(d) : "l"(a), "l"(b));
    return d;
}
__device__ __forceinline__ unsigned long long bcast2(float x) {
    unsigned long long d;
    asm("mov.b64 %0, {%1, %1};" : "=l"(d) : "f"(x));
    return d;
}
__device__ __forceinline__ unsigned long long pack2(float lo, float hi) {
    unsigned long long d;
    asm("mov.b64 %0, {%1, %2};" : "=l"(d) : "f"(lo), "f"(hi));
    return d;
}
__device__ __forceinline__ float hsum2(unsigned long long a) {
    float2 v = *(float2*)&a;
    return v.x + v.y;
}

// ---------------------------------------------------------------------------
// Generic SGEMM:  C[m,n] = sum_k A[m,k] * B[n,k]
// MODE 0: A = x param, epilogue scatters into g_q/g_k/g_v (B*H,C,D) layout
//         (each thread-row's 8 cols = 8 CONSECUTIVE d within one head ->
//          two float4 stores, 32B-aligned)
// MODE 1: A = g_attn (global), plain epilogue into C (d_out)
// 128x128 tile, BK=8, 8x8 per thread (as 8 rows x 4 f32x2 pairs), 256 thr.
// Double-buffered smem: one __syncthreads per k-step.
// Inner product uses packed fma.rn.f32x2: 32 FFMA2 + 8 broadcasts per kk
// instead of 64 FFMA (exact fp32 rounding either way).
// All dims here are multiples of 128 -> no bounds checks.
// ---------------------------------------------------------------------------
template<int MODE>
__global__ __launch_bounds__(256)
void sgemm_nt(const float* __restrict__ A, const float* __restrict__ B,
              float* __restrict__ C, int M, int N, int K)
{
    __shared__ float As[2][8][128];
    __shared__ float Bs[2][8][128];

    const int tid  = threadIdx.x;
    const int brow = blockIdx.y << 7;
    const int bcol = blockIdx.x << 7;
    const int lr   = tid >> 1;          // 0..127
    const int lc   = (tid & 1) << 2;    // 0 or 4
    const int ty   = tid >> 4;          // 0..15
    const int tx   = tid & 15;          // 0..15

    const float* Ap = (MODE == 1) ? g_attn : A;
    const float* Ag = Ap + (size_t)(brow + lr) * K + lc;
    const float* Bg = B  + (size_t)(bcol + lr) * K + lc;

    // acc2[i][p] holds columns {2p, 2p+1} of row i (low word = even col)
    unsigned long long acc2[8][4];
    #pragma unroll
    for (int i = 0; i < 8; i++)
        #pragma unroll
        for (int p = 0; p < 4; p++) acc2[i][p] = 0ull;   // {+0.f, +0.f}

    // Prologue: fill buffer 0
    {
        float4 av = *(const float4*)(Ag);
        float4 bv = *(const float4*)(Bg);
        As[0][lc+0][lr] = av.x; As[0][lc+1][lr] = av.y;
        As[0][lc+2][lr] = av.z; As[0][lc+3][lr] = av.w;
        Bs[0][lc+0][lr] = bv.x; Bs[0][lc+1][lr] = bv.y;
        Bs[0][lc+2][lr] = bv.z; Bs[0][lc+3][lr] = bv.w;
    }
    __syncthreads();

    int buf = 0;
    for (int k0 = 0; k0 < K; k0 += 8) {
        // Prefetch next tile into the other buffer (safe: that buffer was
        // last read two iterations ago, with a barrier since).
        const int nbuf = buf ^ 1;
        if (k0 + 8 < K) {
            float4 av = *(const float4*)(Ag + k0 + 8);
            float4 bv = *(const float4*)(Bg + k0 + 8);
            As[nbuf][lc+0][lr] = av.x; As[nbuf][lc+1][lr] = av.y;
            As[nbuf][lc+2][lr] = av.z; As[nbuf][lc+3][lr] = av.w;
            Bs[nbuf][lc+0][lr] = bv.x; Bs[nbuf][lc+1][lr] = bv.y;
            Bs[nbuf][lc+2][lr] = bv.z; Bs[nbuf][lc+3][lr] = bv.w;
        }

        #pragma unroll
        for (int kk = 0; kk < 8; kk++) {
            float4 a0 = *(const float4*)&As[buf][kk][ty<<3];
            float4 a1 = *(const float4*)&As[buf][kk][(ty<<3)+4];
            // 8 consecutive B floats -> 4 packed pairs (16B-aligned loads)
            ulonglong2 bb0 = *(const ulonglong2*)&Bs[buf][kk][tx<<3];
            ulonglong2 bb1 = *(const ulonglong2*)&Bs[buf][kk][(tx<<3)+4];
            const unsigned long long b0 = bb0.x, b1 = bb0.y;
            const unsigned long long b2 = bb1.x, b3 = bb1.y;
            float ar[8] = {a0.x,a0.y,a0.z,a0.w,a1.x,a1.y,a1.z,a1.w};
            #pragma unroll
            for (int i = 0; i < 8; i++) {
                unsigned long long av = bcast2(ar[i]);
                acc2[i][0] = ffma2(av, b0, acc2[i][0]);
                acc2[i][1] = ffma2(av, b1, acc2[i][1]);
                acc2[i][2] = ffma2(av, b2, acc2[i][2]);
                acc2[i][3] = ffma2(av, b3, acc2[i][3]);
            }
        }
        __syncthreads();   // next buffer's stores complete + this buffer free
        buf = nbuf;
    }

    if (MODE == 0) {
        // f = bcol + 8*tx + j. bcol&1023 is a multiple of 128, so within a
        // thread-row: h = ((bcol&1023) + 8*tx) >> 6 is constant and
        // d = (8*tx & 63) + j runs over 8 consecutive values -> 2x float4.
        const int part = bcol >> 10;
        float* dst = (part == 0) ? g_q : (part == 1) ? g_k : g_v;
        const int rem0 = (bcol & 1023) + (tx << 3);
        const int h    = rem0 >> 6;
        const int d0   = rem0 & 63;        // multiple of 8
        #pragma unroll
        for (int i = 0; i < 8; i++) {
            const float* af = (const float*)acc2[i];   // j = 0..7 in order
            int m = brow + (ty<<3) + i;
            int b = m >> 11, c = m & (CDIM-1);
            float* dp = dst + (((size_t)(b*HDIM + h))*CDIM + c)*DDIM + d0;
            *(float4*)(dp)   = make_float4(af[0], af[1], af[2], af[3]);
            *(float4*)(dp+4) = make_float4(af[4], af[5], af[6], af[7]);
        }
    } else {
        #pragma unroll
        for (int i = 0; i < 8; i++) {
            const float* af = (const float*)acc2[i];
            int m = brow + (ty<<3) + i;
            float* cp = C + (size_t)m*N + bcol + (tx<<3);
            *(float4*)(cp)   = make_float4(af[0], af[1], af[2], af[3]);
            *(float4*)(cp+4) = make_float4(af[4], af[5], af[6], af[7]);
        }
    }
}

// ---------------------------------------------------------------------------
// Flash attention, fp32, causal. Grid: (C/64 q-tiles, B*H). 256 threads.
// qt is REVERSED vs blockIdx.x so the heaviest (diagonal-distant) tiles
// launch first -> better tail behavior across waves (LPT scheduling).
// Tiles: 64 queries x 32 keys. Thread map: ty=tid/16 (4 q rows), tx=tid%16.
// S stage: packed over d as f32x2 pairs. K tile stored PRE-PACKED as u64
// pairs Kp[key][d/2] = {K[key][2p] lo, K[key][2p+1] hi}; per packed step:
// 4 Qs LDS.64 (broadcast) + 2 Kp LDS.64 (2-way conflict, accepted) +
// 8 FFMA2 — vs 28 scalar slots before. Final s = lo+hi of pair accumulator
// (pairwise summation; pure fp32 ops).
// P.V stage: 4x4 micro-tile as 4 rows x 2 f32x2 pairs (packed FFMA2).
// Row reductions via shfl_xor across the 16 lanes sharing a ty.
// ---------------------------------------------------------------------------
__global__ __launch_bounds__(256)
void attn_kernel()
{
    __shared__ float Qs[64][64];                 // u64 reads tx-uniform -> broadcast
    __shared__ unsigned long long Kp[32][33];    // packed d-pairs, row stride 264B (8B-aligned)
    __shared__ float Vs[32][68];                 // u64x2 reads at 4tx conflict-free
    __shared__ float Ps[64][33];                 // reads tx-uniform -> broadcast

    const int tid = threadIdx.x;
    const int qt  = gridDim.x - 1 - blockIdx.x;   // heavy tiles first
    const int bh  = blockIdx.y;                   // b*H + h
    const int ty  = tid >> 4;
    const int tx  = tid & 15;

    const float* Qg = g_q + ((size_t)bh*CDIM + (size_t)qt*64)*DDIM;
    const float* Kg = g_k + (size_t)bh*CDIM*DDIM;
    const float* Vg = g_v + (size_t)bh*CDIM*DDIM;

    // Load Q tile (64x64)
    {
        int r  = tid >> 2;             // 0..63
        int c0 = (tid & 3) << 4;       // 0,16,32,48
        #pragma unroll
        for (int i = 0; i < 4; i++)
            *(float4*)&Qs[r][c0 + 4*i] = *(const float4*)(Qg + r*DDIM + c0 + 4*i);
    }

    float m_i[4], l_i[4];
    // O2[i][p] = packed columns {4tx+2p, 4tx+2p+1} of output row 4ty+i
    unsigned long long O2[4][2];
    #pragma unroll
    for (int i = 0; i < 4; i++) {
        m_i[i] = -CUDART_INF_F;
        l_i[i] = 0.f;
        O2[i][0] = 0ull; O2[i][1] = 0ull;
    }

    const int nkt = 2*qt + 2;          // causal: keys up to and including diagonal
    for (int kt = 0; kt < nkt; kt++) {
        __syncthreads();               // prev iter done reading Kp/Vs/Ps
        {
            int r  = tid >> 3;         // 0..31
            int c0 = (tid & 7) << 3;   // 0..56 (even)
            const float* kp = Kg + (size_t)(kt*32 + r)*DDIM + c0;
            const float* vp = Vg + (size_t)(kt*32 + r)*DDIM + c0;
            float4 k0 = *(const float4*)(kp);
            float4 k1 = *(const float4*)(kp+4);
            float4 v0 = *(const float4*)(vp);
            float4 v1 = *(const float4*)(vp+4);
            int p0i = c0 >> 1;         // pair index base (multiple of 4)
            Kp[r][p0i+0] = pack2(k0.x, k0.y);
            Kp[r][p0i+1] = pack2(k0.z, k0.w);
            Kp[r][p0i+2] = pack2(k1.x, k1.y);
            Kp[r][p0i+3] = pack2(k1.z, k1.w);
            *(float4*)&Vs[r][c0]   = v0;
            *(float4*)&Vs[r][c0+4] = v1;
        }
        __syncthreads();

        // S = Q K^T  (4 rows x 2 cols per thread, packed over d)
        unsigned long long s2[4][2];
        #pragma unroll
        for (int i = 0; i < 4; i++) { s2[i][0] = 0ull; s2[i][1] = 0ull; }
        #pragma unroll 8
        for (int p = 0; p < 32; p++) {
            unsigned long long k0p = Kp[2*tx+0][p];
            unsigned long long k1p = Kp[2*tx+1][p];
            #pragma unroll
            for (int i = 0; i < 4; i++) {
                unsigned long long q2 = *(const unsigned long long*)&Qs[4*ty+i][2*p];
                s2[i][0] = ffma2(q2, k0p, s2[i][0]);
                s2[i][1] = ffma2(q2, k1p, s2[i][1]);
            }
        }
        float s[4][2];
        #pragma unroll
        for (int i = 0; i < 4; i++) {
            s[i][0] = hsum2(s2[i][0]);
            s[i][1] = hsum2(s2[i][1]);
        }

        // causal mask (only diagonal-region tiles need it)
        if (kt >= 2*qt) {
            int kb = kt*32 + 2*tx;
            int qb = qt*64 + 4*ty;
            #pragma unroll
            for (int i = 0; i < 4; i++)
                #pragma unroll
                for (int j = 0; j < 2; j++)
                    if (kb + j > qb + i) s[i][j] = -CUDART_INF_F;
        }

        // online softmax update
        const float scale = 0.125f;    // 1/sqrt(64)
        #pragma unroll
        for (int i = 0; i < 4; i++) {
            float a  = s[i][0]*scale;
            float bb = s[i][1]*scale;
            float tm = fmaxf(a, bb);
            tm = fmaxf(tm, __shfl_xor_sync(0xffffffffu, tm, 1));
            tm = fmaxf(tm, __shfl_xor_sync(0xffffffffu, tm, 2));
            tm = fmaxf(tm, __shfl_xor_sync(0xffffffffu, tm, 4));
            tm = fmaxf(tm, __shfl_xor_sync(0xffffffffu, tm, 8));
            float mn   = fmaxf(m_i[i], tm);     // finite after first tile
            float corr = __expf(m_i[i] - mn);   // -inf -> 0 on first tile
            float p0   = __expf(a  - mn);       // masked -inf -> 0
            float p1   = __expf(bb - mn);
            float rs = p0 + p1;
            rs += __shfl_xor_sync(0xffffffffu, rs, 1);
            rs += __shfl_xor_sync(0xffffffffu, rs, 2);
            rs += __shfl_xor_sync(0xffffffffu, rs, 4);
            rs += __shfl_xor_sync(0xffffffffu, rs, 8);
            l_i[i] = l_i[i]*corr + rs;
            m_i[i] = mn;
            unsigned long long c2 = bcast2(corr);
            O2[i][0] = fmul2(O2[i][0], c2);
            O2[i][1] = fmul2(O2[i][1], c2);
            Ps[4*ty+i][2*tx+0] = p0;
            Ps[4*ty+i][2*tx+1] = p1;
        }
        __syncthreads();

        // O += P V  (4 rows x 2 packed column-pairs per thread, FFMA2)
        #pragma unroll 4
        for (int jk = 0; jk < 32; jk++) {
            // same 16 bytes as a float4 read; lo word = lower column
            ulonglong2 vv2 = *(const ulonglong2*)&Vs[jk][4*tx];
            #pragma unroll
            for (int i = 0; i < 4; i++) {
                unsigned long long bp = bcast2(Ps[4*ty+i][jk]);
                O2[i][0] = ffma2(bp, vv2.x, O2[i][0]);
                O2[i][1] = ffma2(bp, vv2.y, O2[i][1]);
            }
        }
    }

    // epilogue: normalize, write (B*C, H*D) flat layout for the out-proj GEMM
    const int b = bh >> 4, h = bh & 15;
    #pragma unroll
    for (int i = 0; i < 4; i++) {
        float inv = 1.f / l_i[i];
        int q = qt*64 + 4*ty + i;
        const float* of = (const float*)O2[i];   // [c0,c1,c2,c3] in order
        float4 o = make_float4(of[0]*inv, of[1]*inv, of[2]*inv, of[3]*inv);
        *(float4*)&g_attn[((size_t)(b*CDIM + q))*EDIM + h*DDIM + 4*tx] = o;
    }
}

// ---------------------------------------------------------------------------
extern "C" void kernel_launch(void* const* d_in, const int* in_sizes, int n_in,
                              void* d_out, int out_size)
{
    const float* x     = (const float*)d_in[0];   // (4,2048,1024)
    const float* w_qkv = (const float*)d_in[1];   // (3072,1024)
    const float* w_out = (const float*)d_in[2];   // (1024,1024)
    float* out = (float*)d_out;                   // (4,2048,1024)

    dim3 g_qkv(3*EDIM/128, MROWS/128);            // (24, 64)
    sgemm_nt<0><<<g_qkv, 256>>>(x, w_qkv, nullptr, MROWS, 3*EDIM, EDIM);

    dim3 g_at(CDIM/64, BH);                       // (32, 64)
    attn_kernel<<<g_at, 256>>>();

    dim3 g_out(EDIM/128, MROWS/128);              // (8, 64)
    sgemm_nt<1><<<g_out, 256>>>(nullptr, w_out, out, MROWS, EDIM, EDIM);
}

// round 16
// speedup vs baseline: 1.0096x; 1.0096x over previous
#include <cuda_runtime.h>
#include <math_constants.h>

// ---------------------------------------------------------------------------
// MultiHeadSelfAttention: B=4, C=2048, E=1024, H=16, D=64  (all fp32)
//   qkv  = x @ w_qkv^T            (8192 x 3072)
//   attn = causal softmax(q k^T / sqrt(D)) v   per (b,h)
//   out  = flat @ w_out^T         (8192 x 1024)
// ---------------------------------------------------------------------------

#define BDIM    4
#define CDIM    2048
#define EDIM    1024
#define HDIM    16
#define DDIM    64
#define MROWS   (BDIM*CDIM)      // 8192
#define BH      (BDIM*HDIM)      // 64

// Scratch (device globals: allocation-free, graph-capturable)
__device__ float g_q[(size_t)BH*CDIM*DDIM];      // (B*H, C, D)
__device__ float g_k[(size_t)BH*CDIM*DDIM];
__device__ float g_v[(size_t)BH*CDIM*DDIM];
__device__ float g_attn[(size_t)MROWS*EDIM];     // (B*C, H*D)

// ---- Packed f32x2 helpers (Blackwell sm_103a; exact fp32 semantics) -------
__device__ __forceinline__ unsigned long long ffma2(unsigned long long a,
                                                    unsigned long long b,
                                                    unsigned long long c) {
    unsigned long long d;
    asm("fma.rn.f32x2 %0, %1, %2, %3;" : "=l"(d) : "l"(a), "l"(b), "l"(c));
    return d;
}
__device__ __forceinline__ unsigned long long fmul2(unsigned long long a,
                                                    unsigned long long b) {
    unsigned long long d;
    asm("mul.rn.f32x2 %0, %1, %2;" : "=l"(d) : "l"(a), "l"(b));
    return d;
}
__device__ __forceinline__ unsigned long long bcast2(float x) {
    unsigned long long d;
    asm("mov.b64 %0, {%1, %1};" : "=l"(d) : "f"(x));
    return d;
}
__device__ __forceinline__ unsigned long long pack2(float lo, float hi) {
    unsigned long long d;
    asm("mov.b64 %0, {%1, %2};" : "=l"(d) : "f"(lo), "f"(hi));
    return d;
}
__device__ __forceinline__ float hsum2(unsigned long long a) {
    float2 v = *(float2*)&a;
    return v.x + v.y;
}

// ---------------------------------------------------------------------------
// Generic SGEMM:  C[m,n] = sum_k A[m,k] * B[n,k]
// MODE 0: A = x param, epilogue scatters into g_q/g_k/g_v (B*H,C,D) layout
// MODE 1: A = g_attn (global), plain epilogue into C (d_out)
// 128x128 tile, BK=8, 8x8 per thread (as 8 rows x 4 f32x2 pairs), 256 thr.
// Double-buffered smem, LATENCY-HIDING order: LDG(next)->regs, compute(cur),
// STS(next), sync. The STS no longer stalls on the LDG before compute; the
// ~250-580 cyc global latency is hidden behind the ~1k-cyc FFMA2 block.
// ---------------------------------------------------------------------------
template<int MODE>
__global__ __launch_bounds__(256)
void sgemm_nt(const float* __restrict__ A, const float* __restrict__ B,
              float* __restrict__ C, int M, int N, int K)
{
    __shared__ float As[2][8][128];
    __shared__ float Bs[2][8][128];

    const int tid  = threadIdx.x;
    const int brow = blockIdx.y << 7;
    const int bcol = blockIdx.x << 7;
    const int lr   = tid >> 1;          // 0..127
    const int lc   = (tid & 1) << 2;    // 0 or 4
    const int ty   = tid >> 4;          // 0..15
    const int tx   = tid & 15;          // 0..15

    const float* Ap = (MODE == 1) ? g_attn : A;
    const float* Ag = Ap + (size_t)(brow + lr) * K + lc;
    const float* Bg = B  + (size_t)(bcol + lr) * K + lc;

    // acc2[i][p] holds columns {2p, 2p+1} of row i (low word = even col)
    unsigned long long acc2[8][4];
    #pragma unroll
    for (int i = 0; i < 8; i++)
        #pragma unroll
        for (int p = 0; p < 4; p++) acc2[i][p] = 0ull;

    // Prologue: fill buffer 0
    {
        float4 av = *(const float4*)(Ag);
        float4 bv = *(const float4*)(Bg);
        As[0][lc+0][lr] = av.x; As[0][lc+1][lr] = av.y;
        As[0][lc+2][lr] = av.z; As[0][lc+3][lr] = av.w;
        Bs[0][lc+0][lr] = bv.x; Bs[0][lc+1][lr] = bv.y;
        Bs[0][lc+2][lr] = bv.z; Bs[0][lc+3][lr] = bv.w;
    }
    __syncthreads();

    int buf = 0;
    for (int k0 = 0; k0 < K; k0 += 8) {
        const int nbuf = buf ^ 1;
        const bool has_next = (k0 + 8 < K);
        float4 av2, bv2;
        if (has_next) {           // issue LDG early; consumed only after compute
            av2 = *(const float4*)(Ag + k0 + 8);
            bv2 = *(const float4*)(Bg + k0 + 8);
        }

        #pragma unroll
        for (int kk = 0; kk < 8; kk++) {
            float4 a0 = *(const float4*)&As[buf][kk][ty<<3];
            float4 a1 = *(const float4*)&As[buf][kk][(ty<<3)+4];
            ulonglong2 bb0 = *(const ulonglong2*)&Bs[buf][kk][tx<<3];
            ulonglong2 bb1 = *(const ulonglong2*)&Bs[buf][kk][(tx<<3)+4];
            const unsigned long long b0 = bb0.x, b1 = bb0.y;
            const unsigned long long b2 = bb1.x, b3 = bb1.y;
            float ar[8] = {a0.x,a0.y,a0.z,a0.w,a1.x,a1.y,a1.z,a1.w};
            #pragma unroll
            for (int i = 0; i < 8; i++) {
                unsigned long long av = bcast2(ar[i]);
                acc2[i][0] = ffma2(av, b0, acc2[i][0]);
                acc2[i][1] = ffma2(av, b1, acc2[i][1]);
                acc2[i][2] = ffma2(av, b2, acc2[i][2]);
                acc2[i][3] = ffma2(av, b3, acc2[i][3]);
            }
        }

        if (has_next) {           // STS after compute: LDG latency fully hidden
            // nbuf was last read two iterations ago; a barrier has intervened.
            As[nbuf][lc+0][lr] = av2.x; As[nbuf][lc+1][lr] = av2.y;
            As[nbuf][lc+2][lr] = av2.z; As[nbuf][lc+3][lr] = av2.w;
            Bs[nbuf][lc+0][lr] = bv2.x; Bs[nbuf][lc+1][lr] = bv2.y;
            Bs[nbuf][lc+2][lr] = bv2.z; Bs[nbuf][lc+3][lr] = bv2.w;
        }
        __syncthreads();          // stores visible + cur buffer free
        buf = nbuf;
    }

    if (MODE == 0) {
        // f = bcol + 8*tx + j -> h constant per thread-row, d consecutive.
        const int part = bcol >> 10;
        float* dst = (part == 0) ? g_q : (part == 1) ? g_k : g_v;
        const int rem0 = (bcol & 1023) + (tx << 3);
        const int h    = rem0 >> 6;
        const int d0   = rem0 & 63;        // multiple of 8
        #pragma unroll
        for (int i = 0; i < 8; i++) {
            const float* af = (const float*)acc2[i];
            int m = brow + (ty<<3) + i;
            int b = m >> 11, c = m & (CDIM-1);
            float* dp = dst + (((size_t)(b*HDIM + h))*CDIM + c)*DDIM + d0;
            *(float4*)(dp)   = make_float4(af[0], af[1], af[2], af[3]);
            *(float4*)(dp+4) = make_float4(af[4], af[5], af[6], af[7]);
        }
    } else {
        #pragma unroll
        for (int i = 0; i < 8; i++) {
            const float* af = (const float*)acc2[i];
            int m = brow + (ty<<3) + i;
            float* cp = C + (size_t)m*N + bcol + (tx<<3);
            *(float4*)(cp)   = make_float4(af[0], af[1], af[2], af[3]);
            *(float4*)(cp+4) = make_float4(af[4], af[5], af[6], af[7]);
        }
    }
}

// ---------------------------------------------------------------------------
// Flash attention, fp32, causal. Grid: (C/64 q-tiles, B*H). 256 threads.
// LPT ordering (qt reversed). K/V tiles are register-staged: STS at loop
// top from regs, LDG for kt+1 issued right after sync(A) and consumed only
// at the next iteration's STS -> global latency hidden behind S/softmax/PV.
// 3 barriers per k-tile (A: stores visible; B: Ps visible; C: Vs/Ps free).
// ---------------------------------------------------------------------------
__global__ __launch_bounds__(256)
void attn_kernel()
{
    __shared__ float Qs[64][64];                 // u64 reads tx-uniform -> broadcast
    __shared__ unsigned long long Kp[32][33];    // packed d-pairs, 264B rows
    __shared__ float Vs[32][68];                 // u64x2 reads at 4tx conflict-free
    __shared__ float Ps[64][33];                 // reads tx-uniform -> broadcast

    const int tid = threadIdx.x;
    const int qt  = gridDim.x - 1 - blockIdx.x;   // heavy tiles first
    const int bh  = blockIdx.y;                   // b*H + h
    const int ty  = tid >> 4;
    const int tx  = tid & 15;

    const float* Qg = g_q + ((size_t)bh*CDIM + (size_t)qt*64)*DDIM;
    const float* Kg = g_k + (size_t)bh*CDIM*DDIM;
    const float* Vg = g_v + (size_t)bh*CDIM*DDIM;

    // Load Q tile (64x64)
    {
        int r  = tid >> 2;             // 0..63
        int c0 = (tid & 3) << 4;       // 0,16,32,48
        #pragma unroll
        for (int i = 0; i < 4; i++)
            *(float4*)&Qs[r][c0 + 4*i] = *(const float4*)(Qg + r*DDIM + c0 + 4*i);
    }

    // loader lane constants
    const int lr  = tid >> 3;          // 0..31 (key row within tile)
    const int lc0 = (tid & 7) << 3;    // 0..56 (even)
    const int lp0 = lc0 >> 1;          // pair index base
    const float* kbase = Kg + (size_t)lr*DDIM + lc0;
    const float* vbase = Vg + (size_t)lr*DDIM + lc0;

    float m_i[4], l_i[4];
    unsigned long long O2[4][2];
    #pragma unroll
    for (int i = 0; i < 4; i++) {
        m_i[i] = -CUDART_INF_F;
        l_i[i] = 0.f;
        O2[i][0] = 0ull; O2[i][1] = 0ull;
    }

    const int nkt = 2*qt + 2;          // causal: keys up to and including diagonal

    // Prefetch tile 0 into registers
    float4 k0r = *(const float4*)(kbase);
    float4 k1r = *(const float4*)(kbase+4);
    float4 v0r = *(const float4*)(vbase);
    float4 v1r = *(const float4*)(vbase+4);

    for (int kt = 0; kt < nkt; kt++) {
        // STS current tile from registers
        Kp[lr][lp0+0] = pack2(k0r.x, k0r.y);
        Kp[lr][lp0+1] = pack2(k0r.z, k0r.w);
        Kp[lr][lp0+2] = pack2(k1r.x, k1r.y);
        Kp[lr][lp0+3] = pack2(k1r.z, k1r.w);
        *(float4*)&Vs[lr][lc0]   = v0r;
        *(float4*)&Vs[lr][lc0+4] = v1r;
        __syncthreads();               // (A) stores visible

        // Issue LDG for NEXT tile; consumed only at next iteration's STS.
        if (kt + 1 < nkt) {
            const size_t off = (size_t)(kt+1)*32*DDIM;
            k0r = *(const float4*)(kbase + off);
            k1r = *(const float4*)(kbase + off + 4);
            v0r = *(const float4*)(vbase + off);
            v1r = *(const float4*)(vbase + off + 4);
        }

        // S = Q K^T  (4 rows x 2 cols per thread, packed over d)
        unsigned long long s2[4][2];
        #pragma unroll
        for (int i = 0; i < 4; i++) { s2[i][0] = 0ull; s2[i][1] = 0ull; }
        #pragma unroll 8
        for (int p = 0; p < 32; p++) {
            unsigned long long k0p = Kp[2*tx+0][p];
            unsigned long long k1p = Kp[2*tx+1][p];
            #pragma unroll
            for (int i = 0; i < 4; i++) {
                unsigned long long q2 = *(const unsigned long long*)&Qs[4*ty+i][2*p];
                s2[i][0] = ffma2(q2, k0p, s2[i][0]);
                s2[i][1] = ffma2(q2, k1p, s2[i][1]);
            }
        }
        float s[4][2];
        #pragma unroll
        for (int i = 0; i < 4; i++) {
            s[i][0] = hsum2(s2[i][0]);
            s[i][1] = hsum2(s2[i][1]);
        }

        // causal mask (only diagonal-region tiles need it)
        if (kt >= 2*qt) {
            int kb = kt*32 + 2*tx;
            int qb = qt*64 + 4*ty;
            #pragma unroll
            for (int i = 0; i < 4; i++)
                #pragma unroll
                for (int j = 0; j < 2; j++)
                    if (kb + j > qb + i) s[i][j] = -CUDART_INF_F;
        }

        // online softmax update
        const float scale = 0.125f;    // 1/sqrt(64)
        #pragma unroll
        for (int i = 0; i < 4; i++) {
            float a  = s[i][0]*scale;
            float bb = s[i][1]*scale;
            float tm = fmaxf(a, bb);
            tm = fmaxf(tm, __shfl_xor_sync(0xffffffffu, tm, 1));
            tm = fmaxf(tm, __shfl_xor_sync(0xffffffffu, tm, 2));
            tm = fmaxf(tm, __shfl_xor_sync(0xffffffffu, tm, 4));
            tm = fmaxf(tm, __shfl_xor_sync(0xffffffffu, tm, 8));
            float mn   = fmaxf(m_i[i], tm);     // finite after first tile
            float corr = __expf(m_i[i] - mn);   // -inf -> 0 on first tile
            float p0   = __expf(a  - mn);       // masked -inf -> 0
            float p1   = __expf(bb - mn);
            float rs = p0 + p1;
            rs += __shfl_xor_sync(0xffffffffu, rs, 1);
            rs += __shfl_xor_sync(0xffffffffu, rs, 2);
            rs += __shfl_xor_sync(0xffffffffu, rs, 4);
            rs += __shfl_xor_sync(0xffffffffu, rs, 8);
            l_i[i] = l_i[i]*corr + rs;
            m_i[i] = mn;
            unsigned long long c2 = bcast2(corr);
            O2[i][0] = fmul2(O2[i][0], c2);
            O2[i][1] = fmul2(O2[i][1], c2);
            Ps[4*ty+i][2*tx+0] = p0;
            Ps[4*ty+i][2*tx+1] = p1;
        }
        __syncthreads();               // (B) Ps visible; Kp reads done

        // O += P V  (4 rows x 2 packed column-pairs per thread, FFMA2)
        #pragma unroll 4
        for (int jk = 0; jk < 32; jk++) {
            ulonglong2 vv2 = *(const ulonglong2*)&Vs[jk][4*tx];
            #pragma unroll
            for (int i = 0; i < 4; i++) {
                unsigned long long bp = bcast2(Ps[4*ty+i][jk]);
                O2[i][0] = ffma2(bp, vv2.x, O2[i][0]);
                O2[i][1] = ffma2(bp, vv2.y, O2[i][1]);
            }
        }
        __syncthreads();               // (C) Vs/Ps free before next STS
    }

    // epilogue: normalize, write (B*C, H*D) flat layout for the out-proj GEMM
    const int b = bh >> 4, h = bh & 15;
    #pragma unroll
    for (int i = 0; i < 4; i++) {
        float inv = 1.f / l_i[i];
        int q = qt*64 + 4*ty + i;
        const float* of = (const float*)O2[i];
        float4 o = make_float4(of[0]*inv, of[1]*inv, of[2]*inv, of[3]*inv);
        *(float4*)&g_attn[((size_t)(b*CDIM + q))*EDIM + h*DDIM + 4*tx] = o;
    }
}

// ---------------------------------------------------------------------------
extern "C" void kernel_launch(void* const* d_in, const int* in_sizes, int n_in,
                              void* d_out, int out_size)
{
    const float* x     = (const float*)d_in[0];   // (4,2048,1024)
    const float* w_qkv = (const float*)d_in[1];   // (3072,1024)
    const float* w_out = (const float*)d_in[2];   // (1024,1024)
    float* out = (float*)d_out;                   // (4,2048,1024)

    dim3 g_qkv(3*EDIM/128, MROWS/128);            // (24, 64)
    sgemm_nt<0><<<g_qkv, 256>>>(x, w_qkv, nullptr, MROWS, 3*EDIM, EDIM);

    dim3 g_at(CDIM/64, BH);                       // (32, 64)
    attn_kernel<<<g_at, 256>>>();

    dim3 g_out(EDIM/128, MROWS/128);              // (8, 64)
    sgemm_nt<1><<<g_out, 256>>>(nullptr, w_out, out, MROWS, EDIM, EDIM);
}